// round 13
// baseline (speedup 1.0000x reference)
#include <cuda_runtime.h>
#include <cuda_fp16.h>
#include <cstdint>
#include <math.h>

// Problem constants
#define BB   8
#define SS   8192
#define HH   768
#define MM   (BB*SS)      // 65536 GEMM rows
#define KK   768          // GEMM K
#define NT   16           // number of 48-wide a/g column tiles (768/48)
#define LAM  0.1f

#define BKT  32           // GEMM k-tile (fp16 elements; 64B per row, 4 granules)
#define KITR (KK/BKT)     // 24
#define BNR  96           // B rows per tile (48 a + 48 g)
#define A_STG_H (128*32)  // 4096 halves
#define B_STG_H (BNR*32)  // 3072 halves
#define STG_H   (A_STG_H + B_STG_H)       // 7168 halves = 14336 B
#define CS_BYTES (128*100*4)              // 51200
#define XS_OFF   CS_BYTES                 // Xs after Cs
#define SMEM_GEMM_BYTES (CS_BYTES + 128*48*4)   // 75776 (>3*14336 stages; 3 CTAs/SM)

// ---------------- device scratch ----------------
__device__ __half g_v[(size_t)MM*HH];       // silu(x*D + conv) in fp16 (100MB)
__device__ __half g_w[NT*BNR*KK];           // W permuted: [nT][96 rows: 48 a | 48 g][K]
__device__ float  g_tapv[HH*SS];
__device__ int    g_tapi[HH*SS];
__device__ int    g_nnz[HH];

// ---------------- helpers ----------------
__device__ __forceinline__ void cp16(void* s, const void* g) {
    uint32_t sa = (uint32_t)__cvta_generic_to_shared(s);
    asm volatile("cp.async.cg.shared.global [%0], [%1], 16;" :: "r"(sa), "l"(g));
}
__device__ __forceinline__ void cp_commit() { asm volatile("cp.async.commit_group;"); }

__device__ __forceinline__ void ldmx4(uint32_t& r0, uint32_t& r1, uint32_t& r2, uint32_t& r3,
                                      uint32_t addr) {
    asm volatile("ldmatrix.sync.aligned.m8n8.x4.shared.b16 {%0,%1,%2,%3}, [%4];"
                 : "=r"(r0), "=r"(r1), "=r"(r2), "=r"(r3) : "r"(addr));
}

__device__ __forceinline__ void mma_f16(float c[4], const uint32_t a[4], const uint32_t b[2]) {
    asm("mma.sync.aligned.m16n8k16.row.col.f32.f16.f16.f32 "
        "{%0,%1,%2,%3}, {%4,%5,%6,%7}, {%8,%9}, {%0,%1,%2,%3};"
        : "+f"(c[0]), "+f"(c[1]), "+f"(c[2]), "+f"(c[3])
        : "r"(a[0]), "r"(a[1]), "r"(a[2]), "r"(a[3]), "r"(b[0]), "r"(b[1]));
}

// ---------------- kernel 1: soft-threshold + compact taps ----------------
__global__ void k_taps(const float* __restrict__ ker) {
    __shared__ int cnt;
    const int h = blockIdx.x;
    if (threadIdx.x == 0) cnt = 0;
    __syncthreads();
    const float* kr = ker + (size_t)h*SS;
    for (int t = threadIdx.x; t < SS; t += blockDim.x) {
        float kv = kr[t];
        float av = fabsf(kv) - LAM;
        if (av > 0.0f) {
            int p = atomicAdd(&cnt, 1);
            g_tapv[(size_t)h*SS + p] = copysignf(av, kv);
            g_tapi[(size_t)h*SS + p] = t;
        }
    }
    __syncthreads();
    if (threadIdx.x == 0) g_nnz[h] = cnt;
}

// ---------------- kernel 2: permute W into a/g-paired tiles (fp16) ------------
// g_w[nT][r][k]: r<48 -> W[nT*48 + r] ('a'); r>=48 -> W[768 + nT*48 + (r-48)] ('g')
__global__ void k_wprep(const float* __restrict__ W) {
    int idx = blockIdx.x * blockDim.x + threadIdx.x;
    if (idx >= NT*BNR*KK) return;
    int k  = idx % KK;
    int r  = (idx / KK) % BNR;
    int nT = idx / (BNR*KK);
    int srcRow = (r < 48) ? (nT*48 + r) : (768 + nT*48 + (r - 48));
    g_w[idx] = __float2half_rn(W[(size_t)srcRow*KK + k]);
}

// ---------------- kernel 3: v = silu(x*D + sparse_conv) -> fp16 ---------------
__global__ void k_v(const float* __restrict__ x, const float* __restrict__ D) {
    int i4 = blockIdx.x * blockDim.x + threadIdx.x;
    int m  = i4 / (HH/4);
    int h0 = (i4 - m*(HH/4)) * 4;
    const float4 xv = *(const float4*)(x + (size_t)m*HH + h0);
    const float4 dv = *(const float4*)(D + h0);
    const int4  nn = *(const int4*)(g_nnz + h0);
    float y[4] = { xv.x*dv.x, xv.y*dv.y, xv.z*dv.z, xv.w*dv.w };
    if (nn.x | nn.y | nn.z | nn.w) {
        const int s = m & (SS-1);
        const int nnc[4] = { nn.x, nn.y, nn.z, nn.w };
        for (int c = 0; c < 4; c++) {
            const int h = h0 + c;
            for (int j = 0; j < nnc[c]; j++) {
                int t = g_tapi[(size_t)h*SS + j];
                if (t <= s) y[c] += g_tapv[(size_t)h*SS + j] * x[(size_t)(m - t)*HH + h];
            }
        }
    }
    float sv[4];
    #pragma unroll
    for (int c = 0; c < 4; c++) sv[c] = y[c] / (1.0f + __expf(-y[c]));
    *(__half2*)(g_v + (size_t)m*HH + h0    ) = __floats2half2_rn(sv[0], sv[1]);
    *(__half2*)(g_v + (size_t)m*HH + h0 + 2) = __floats2half2_rn(sv[2], sv[3]);
}

// ---------------- kernel 4: fp16 GEMM + bias + GLU + residual -----------------
// CTA tile: C[128 x 96]; local cols [0,48)=a, [48,96)=g (same h).
// 8 warps: 4 in M (32 rows) x 2 in N (48 cols). BKT=32, 3-stage, 1 barrier/kt.
// Swizzle for 64B rows: granule g' = cc ^ ((r>>1)&3)  (4 x 16B granules/row).
__global__ void __launch_bounds__(256, 3)
k_gemm(const float* __restrict__ x, const float* __restrict__ bias,
       float* __restrict__ out) {
    extern __shared__ __align__(16) char smraw[];
    __half* St = (__half*)smraw;               // 3 stages of [A 128x32 | B 96x32]

    const int tid  = threadIdx.x;
    const int warp = tid >> 5, lane = tid & 31;
    const int g    = lane >> 2, t = lane & 3;
    const int wm   = (warp & 3) * 32;    // warp M offset (4 warps in M)
    const int wn   = (warp >> 2) * 48;   // warp N offset (2 warps in N)
    const int nT   = blockIdx.x;
    const int m0   = blockIdx.y * 128;

    const __half* gA = g_v + (size_t)m0*KK;
    const __half* gB = g_w + (size_t)nT*BNR*KK;

    // ldmatrix lane decomposition: matrix j = lane>>3, row-in-matrix ri = lane&7
    const int jl = (lane >> 3) & 1;
    const int jh = (lane >> 3) >> 1;
    const int ri = lane & 7;
    const int ar0 = wm + jl*8 + ri;      // A row for mt=0 (mt=1 adds 16)
    int brow[3];                          // B rows for x4 groups p=0..2 (nt = 2p+jh)
    #pragma unroll
    for (int p = 0; p < 3; p++) brow[p] = wn + (2*p + jh)*8 + ri;

    const uint32_t smS = (uint32_t)__cvta_generic_to_shared(St);

    float c[2][6][4];
    #pragma unroll
    for (int i = 0; i < 2; i++)
        #pragma unroll
        for (int j = 0; j < 6; j++)
            #pragma unroll
            for (int q = 0; q < 4; q++) c[i][j][q] = 0.0f;

    // ---- async stage loader: 224 rows x 4 chunks(16B) = 896 cp16 / 256 thr
    // elem (row r, chunk cc) at stage + r*64B + ((cc ^ ((r>>1)&3))*16B
    #define ISSUE_STAGE(stg, kt_)                                              \
    {                                                                          \
        const int k0_ = (kt_) * BKT;                                           \
        _Pragma("unroll")                                                      \
        for (int i_ = 0; i_ < 4; i_++) {                                       \
            int li_ = tid + i_*256;                                            \
            if (li_ < 896) {                                                   \
                int r_  = li_ >> 2, cc_ = li_ & 3;                             \
                const __half* src_ = (r_ < 128)                                \
                    ? gA + (size_t)r_*KK + k0_ + cc_*8                         \
                    : gB + (size_t)(r_-128)*KK + k0_ + cc_*8;                  \
                cp16(St + (stg)*STG_H + r_*32 + ((cc_ ^ ((r_>>1) & 3)) << 3), src_); \
            }                                                                  \
        }                                                                      \
    }

    ISSUE_STAGE(0, 0); cp_commit();
    ISSUE_STAGE(1, 1); cp_commit();

    for (int kt = 0; kt < KITR; kt++) {
        asm volatile("cp.async.wait_group 1;");
        __syncthreads();
        if (kt + 2 < KITR) { ISSUE_STAGE((kt+2)%3, kt+2); }
        cp_commit();

        const uint32_t A_ = smS + (uint32_t)((kt%3)*STG_H)*2u;
        const uint32_t B_ = A_ + (uint32_t)A_STG_H*2u;

        #pragma unroll
        for (int ks = 0; ks < 2; ks++) {     // 2 x k16 per stage
            uint32_t af[2][4], bf[6][2];
            const int kcA = 2*ks + jh;       // granule in [0,4)
            #pragma unroll
            for (int mt = 0; mt < 2; mt++) {
                int r_ = ar0 + mt*16;
                uint32_t addr = A_ + (uint32_t)(r_*64 + ((kcA ^ ((r_>>1) & 3)) << 4));
                ldmx4(af[mt][0], af[mt][1], af[mt][2], af[mt][3], addr);
            }
            const int kcB = 2*ks + jl;
            #pragma unroll
            for (int p = 0; p < 3; p++) {
                int r_ = brow[p];
                uint32_t addr = B_ + (uint32_t)(r_*64 + ((kcB ^ ((r_>>1) & 3)) << 4));
                ldmx4(bf[2*p][0], bf[2*p][1], bf[2*p+1][0], bf[2*p+1][1], addr);
            }
            #pragma unroll
            for (int mt = 0; mt < 2; mt++)
                #pragma unroll
                for (int nt = 0; nt < 6; nt++)
                    mma_f16(c[mt][nt], af[mt], bf[nt]);
        }
    }
    asm volatile("cp.async.wait_group 0;");
    __syncthreads();

    // ---- prefetch x-residual tile (128 rows x 48 floats = 24KB) into smem
    float* Xs = (float*)(smraw + XS_OFF);
    {
        const float* gx = x + (size_t)m0*HH + nT*48;
        #pragma unroll
        for (int i = 0; i < 6; i++) {
            int li = tid + i*256;             // 128 rows x 12 chunks(16B) = 1536
            int r = li / 12, cc = li - r*12;
            cp16(Xs + r*48 + cc*4, gx + (size_t)r*HH + cc*4);
        }
        cp_commit();
    }

    // ---- stage C through smem so (a,g) pairs are visible to one thread ----
    float* Cs = (float*)smraw;            // [128][100] = 51.2KB
    #pragma unroll
    for (int mt = 0; mt < 2; mt++)
        #pragma unroll
        for (int nt = 0; nt < 6; nt++) {
            int r = wm + mt*16 + g, cc = wn + nt*8 + 2*t;
            Cs[ r   *100 + cc    ] = c[mt][nt][0];
            Cs[ r   *100 + cc + 1] = c[mt][nt][1];
            Cs[(r+8)*100 + cc    ] = c[mt][nt][2];
            Cs[(r+8)*100 + cc + 1] = c[mt][nt][3];
        }
    asm volatile("cp.async.wait_group 0;");
    __syncthreads();

    // ---- bias + GLU + residual, write final output ----
    #pragma unroll
    for (int i = 0; i < 24; i++) {
        int idx = i*256 + tid;            // 128*48 outputs
        int r = idx / 48, j = idx - r*48;
        int h = nT*48 + j;
        float a  = Cs[r*100 + j     ] + bias[h];
        float gg = Cs[r*100 + j + 48] + bias[h + 768];
        float sg = 1.0f / (1.0f + __expf(-gg));
        out[(size_t)(m0 + r)*HH + h] = a * sg + Xs[r*48 + j];
    }
    #undef ISSUE_STAGE
}

// ---------------- launch ----------------
extern "C" void kernel_launch(void* const* d_in, const int* in_sizes, int n_in,
                              void* d_out, int out_size) {
    const float* x    = (const float*)d_in[0];   // (8, 8192, 768)
    const float* ker  = (const float*)d_in[1];   // (1, 768, 8192)
    const float* D    = (const float*)d_in[2];   // (1, 768)
    const float* W    = (const float*)d_in[3];   // (1536, 768)
    const float* bias = (const float*)d_in[4];   // (1536,)
    float* out = (float*)d_out;                  // (8, 8192, 768)

    k_taps<<<HH, 256>>>(ker);
    k_wprep<<<(NT*BNR*KK + 255)/256, 256>>>(W);
    k_v<<<(MM*(HH/4))/256, 256>>>(x, D);

    (void)cudaFuncSetAttribute(k_gemm, cudaFuncAttributeMaxDynamicSharedMemorySize,
                               SMEM_GEMM_BYTES);
    dim3 grid(NT, MM/128);
    k_gemm<<<grid, 256, SMEM_GEMM_BYTES>>>(x, bias, out);
}

// round 14
// speedup vs baseline: 1.0663x; 1.0663x over previous
#include <cuda_runtime.h>
#include <cuda_fp16.h>
#include <cstdint>
#include <math.h>

// Problem constants
#define BB   8
#define SS   8192
#define HH   768
#define MM   (BB*SS)      // 65536 GEMM rows
#define KK   768          // GEMM K
#define NT   24           // number of 32-wide a/g column tiles (768/32)
#define LAM  0.1f

#define BKT  64           // GEMM k-tile (fp16 elements; 128B per row)
#define KITR (KK/BKT)     // 12
#define BNR  64           // B rows per tile (32 a + 32 g)
#define A_STG_H (128*64)  // 8192 halves
#define B_STG_H (BNR*64)  // 4096 halves
#define STG_H   (A_STG_H + B_STG_H)       // 12288 halves = 24KB
#define SMEM_GEMM_BYTES (3*STG_H*2)       // 73728 -> 72KB (3 CTAs/SM = 216KB)
#define XS_OFF  34816     // byte offset of x-prefetch tile (after Cs 128*68*4B)

#define WPREP_N    (NT*BNR*KK)            // 1179648
#define WPREP_BLKS ((WPREP_N + 255)/256)  // 4608

// ---------------- device scratch ----------------
__device__ __half g_v[(size_t)MM*HH];       // silu(x*D + conv) in fp16 (100MB)
__device__ __half g_w[NT*BNR*KK];           // W permuted: [nT][64 rows: 32 a | 32 g][K]
__device__ float  g_tapv[HH*SS];
__device__ int    g_tapi[HH*SS];
__device__ int    g_nnz[HH];

// ---------------- helpers ----------------
__device__ __forceinline__ void cp16(void* s, const void* g) {
    uint32_t sa = (uint32_t)__cvta_generic_to_shared(s);
    asm volatile("cp.async.cg.shared.global [%0], [%1], 16;" :: "r"(sa), "l"(g));
}
__device__ __forceinline__ void cp_commit() { asm volatile("cp.async.commit_group;"); }

__device__ __forceinline__ void ldmx4(uint32_t& r0, uint32_t& r1, uint32_t& r2, uint32_t& r3,
                                      uint32_t addr) {
    asm volatile("ldmatrix.sync.aligned.m8n8.x4.shared.b16 {%0,%1,%2,%3}, [%4];"
                 : "=r"(r0), "=r"(r1), "=r"(r2), "=r"(r3) : "r"(addr));
}

__device__ __forceinline__ void mma_f16(float c[4], const uint32_t a[4], const uint32_t b[2]) {
    asm("mma.sync.aligned.m16n8k16.row.col.f32.f16.f16.f32 "
        "{%0,%1,%2,%3}, {%4,%5,%6,%7}, {%8,%9}, {%0,%1,%2,%3};"
        : "+f"(c[0]), "+f"(c[1]), "+f"(c[2]), "+f"(c[3])
        : "r"(a[0]), "r"(a[1]), "r"(a[2]), "r"(a[3]), "r"(b[0]), "r"(b[1]));
}

// ---------------- kernel 1: fused soft-threshold taps + W permute -------------
// Blocks [0, HH): per-channel tap compaction.
// Blocks [HH, HH+WPREP_BLKS): W permute/convert (independent work, runs concurrently).
__global__ void k_prep(const float* __restrict__ ker, const float* __restrict__ W) {
    if (blockIdx.x < HH) {
        __shared__ int cnt;
        const int h = blockIdx.x;
        if (threadIdx.x == 0) cnt = 0;
        __syncthreads();
        const float* kr = ker + (size_t)h*SS;
        for (int t = threadIdx.x; t < SS; t += blockDim.x) {
            float kv = kr[t];
            float av = fabsf(kv) - LAM;
            if (av > 0.0f) {
                int p = atomicAdd(&cnt, 1);
                g_tapv[(size_t)h*SS + p] = copysignf(av, kv);
                g_tapi[(size_t)h*SS + p] = t;
            }
        }
        __syncthreads();
        if (threadIdx.x == 0) g_nnz[h] = cnt;
    } else {
        int idx = (blockIdx.x - HH) * blockDim.x + threadIdx.x;
        if (idx >= WPREP_N) return;
        int k  = idx % KK;
        int r  = (idx / KK) % BNR;
        int nT = idx / (BNR*KK);
        int srcRow = (r < 32) ? (nT*32 + r) : (768 + nT*32 + (r - 32));
        g_w[idx] = __float2half_rn(W[(size_t)srcRow*KK + k]);
    }
}

// ---------------- kernel 2: v = silu(x*D + sparse_conv) -> fp16, 8 h/thread ---
__global__ void k_v(const float* __restrict__ x, const float* __restrict__ D) {
    int i8 = blockIdx.x * blockDim.x + threadIdx.x;   // index over M*H/8
    int m  = i8 / (HH/8);
    int h0 = (i8 - m*(HH/8)) * 8;
    const float4 xv0 = *(const float4*)(x + (size_t)m*HH + h0);
    const float4 xv1 = *(const float4*)(x + (size_t)m*HH + h0 + 4);
    const float4 dv0 = *(const float4*)(D + h0);
    const float4 dv1 = *(const float4*)(D + h0 + 4);
    float y[8] = { xv0.x*dv0.x, xv0.y*dv0.y, xv0.z*dv0.z, xv0.w*dv0.w,
                   xv1.x*dv1.x, xv1.y*dv1.y, xv1.z*dv1.z, xv1.w*dv1.w };
    const int4 nn0 = *(const int4*)(g_nnz + h0);
    const int4 nn1 = *(const int4*)(g_nnz + h0 + 4);
    if (nn0.x|nn0.y|nn0.z|nn0.w|nn1.x|nn1.y|nn1.z|nn1.w) {  // general conv path
        const int s = m & (SS-1);
        const int nnc[8] = { nn0.x, nn0.y, nn0.z, nn0.w, nn1.x, nn1.y, nn1.z, nn1.w };
        for (int c = 0; c < 8; c++) {
            const int h = h0 + c;
            for (int j = 0; j < nnc[c]; j++) {
                int t = g_tapi[(size_t)h*SS + j];
                if (t <= s) y[c] += g_tapv[(size_t)h*SS + j] * x[(size_t)(m - t)*HH + h];
            }
        }
    }
    __half2 o[4];
    #pragma unroll
    for (int c = 0; c < 4; c++) {
        float a = y[2*c],   sa = a / (1.0f + __expf(-a));
        float b = y[2*c+1], sb = b / (1.0f + __expf(-b));
        o[c] = __floats2half2_rn(sa, sb);
    }
    *(uint4*)(g_v + (size_t)m*HH + h0) = *(uint4*)o;   // single 16B store
}

// ---------------- kernel 3: fp16 GEMM + bias + GLU + residual (R12 champion) --
__global__ void __launch_bounds__(256, 3)
k_gemm(const float* __restrict__ x, const float* __restrict__ bias,
       float* __restrict__ out) {
    extern __shared__ __align__(16) char smraw[];
    __half* St = (__half*)smraw;               // 3 stages of [A 128x64 | B 64x64]

    const int tid  = threadIdx.x;
    const int warp = tid >> 5, lane = tid & 31;
    const int g    = lane >> 2, t = lane & 3;
    const int wm   = (warp & 3) * 32;    // warp M offset (4 warps in M)
    const int wn   = (warp >> 2) * 32;   // warp N offset (2 warps in N)
    const int nT   = blockIdx.x;
    const int m0   = blockIdx.y * 128;

    const __half* gA = g_v + (size_t)m0*KK;
    const __half* gB = g_w + (size_t)nT*BNR*KK;

    const int jl = (lane >> 3) & 1;
    const int jh = (lane >> 3) >> 1;
    const int ri = lane & 7;
    const int ar0 = wm + jl*8 + ri;
    int brow[2];
    #pragma unroll
    for (int p = 0; p < 2; p++) brow[p] = wn + (2*p + jh)*8 + ri;

    const uint32_t smS = (uint32_t)__cvta_generic_to_shared(St);

    float c[2][4][4];
    #pragma unroll
    for (int i = 0; i < 2; i++)
        #pragma unroll
        for (int j = 0; j < 4; j++)
            #pragma unroll
            for (int q = 0; q < 4; q++) c[i][j][q] = 0.0f;

    #define ISSUE_STAGE(stg, kt_)                                              \
    {                                                                          \
        const int k0_ = (kt_) * BKT;                                           \
        _Pragma("unroll")                                                      \
        for (int i_ = 0; i_ < 6; i_++) {                                       \
            int li_ = tid + i_*256;                                            \
            int r_  = li_ >> 3, cc_ = li_ & 7;                                 \
            const __half* src_ = (r_ < 128)                                    \
                ? gA + (size_t)r_*KK + k0_ + cc_*8                             \
                : gB + (size_t)(r_-128)*KK + k0_ + cc_*8;                      \
            cp16(St + (stg)*STG_H + r_*64 + ((cc_ ^ (r_ & 7)) << 3), src_);    \
        }                                                                      \
    }

    ISSUE_STAGE(0, 0); cp_commit();
    ISSUE_STAGE(1, 1); cp_commit();

    for (int kt = 0; kt < KITR; kt++) {
        asm volatile("cp.async.wait_group 1;");
        __syncthreads();
        if (kt + 2 < KITR) { ISSUE_STAGE((kt+2)%3, kt+2); }
        cp_commit();

        const uint32_t A_ = smS + (uint32_t)((kt%3)*STG_H)*2u;
        const uint32_t B_ = A_ + (uint32_t)A_STG_H*2u;

        #pragma unroll
        for (int ks = 0; ks < 4; ks++) {
            uint32_t af[2][4], bf[4][2];
            const int kcA = 2*ks + jh;
            #pragma unroll
            for (int mt = 0; mt < 2; mt++) {
                int r_ = ar0 + mt*16;
                uint32_t addr = A_ + (uint32_t)(r_*128 + ((kcA ^ (r_ & 7)) << 4));
                ldmx4(af[mt][0], af[mt][1], af[mt][2], af[mt][3], addr);
            }
            const int kcB = 2*ks + jl;
            #pragma unroll
            for (int p = 0; p < 2; p++) {
                int r_ = brow[p];
                uint32_t addr = B_ + (uint32_t)(r_*128 + ((kcB ^ (r_ & 7)) << 4));
                ldmx4(bf[2*p][0], bf[2*p][1], bf[2*p+1][0], bf[2*p+1][1], addr);
            }
            #pragma unroll
            for (int mt = 0; mt < 2; mt++)
                #pragma unroll
                for (int nt = 0; nt < 4; nt++)
                    mma_f16(c[mt][nt], af[mt], bf[nt]);
        }
    }
    asm volatile("cp.async.wait_group 0;");
    __syncthreads();

    // ---- prefetch x-residual tile (128 rows x 32 floats = 16KB) into dead smem
    float* Xs = (float*)(smraw + XS_OFF);
    {
        const float* gx = x + (size_t)m0*HH + nT*32;
        #pragma unroll
        for (int i = 0; i < 4; i++) {
            int li = tid + i*256;
            int r = li >> 3, cc = li & 7;
            cp16(Xs + r*32 + cc*4, gx + (size_t)r*HH + cc*4);
        }
        cp_commit();
    }

    // ---- stage C through smem so (a,g) pairs are visible to one thread ----
    float* Cs = (float*)smraw;            // [128][68] = 34.8KB
    #pragma unroll
    for (int mt = 0; mt < 2; mt++)
        #pragma unroll
        for (int nt = 0; nt < 4; nt++) {
            int r = wm + mt*16 + g, cc = wn + nt*8 + 2*t;
            Cs[ r   *68 + cc    ] = c[mt][nt][0];
            Cs[ r   *68 + cc + 1] = c[mt][nt][1];
            Cs[(r+8)*68 + cc    ] = c[mt][nt][2];
            Cs[(r+8)*68 + cc + 1] = c[mt][nt][3];
        }
    asm volatile("cp.async.wait_group 0;");
    __syncthreads();

    // ---- bias + GLU + residual, write final output ----
    #pragma unroll
    for (int i = 0; i < 16; i++) {
        int idx = i*256 + tid;            // 128*32 outputs
        int r = idx >> 5, j = idx & 31;
        int h = nT*32 + j;
        float a  = Cs[r*68 + j     ] + bias[h];
        float gg = Cs[r*68 + j + 32] + bias[h + 768];
        float sg = 1.0f / (1.0f + __expf(-gg));
        out[(size_t)(m0 + r)*HH + h] = a * sg + Xs[r*32 + j];
    }
    #undef ISSUE_STAGE
}

// ---------------- launch ----------------
extern "C" void kernel_launch(void* const* d_in, const int* in_sizes, int n_in,
                              void* d_out, int out_size) {
    const float* x    = (const float*)d_in[0];   // (8, 8192, 768)
    const float* ker  = (const float*)d_in[1];   // (1, 768, 8192)
    const float* D    = (const float*)d_in[2];   // (1, 768)
    const float* W    = (const float*)d_in[3];   // (1536, 768)
    const float* bias = (const float*)d_in[4];   // (1536,)
    float* out = (float*)d_out;                  // (8, 8192, 768)

    k_prep<<<HH + WPREP_BLKS, 256>>>(ker, W);
    k_v<<<(MM*(HH/8))/256, 256>>>(x, D);

    (void)cudaFuncSetAttribute(k_gemm, cudaFuncAttributeMaxDynamicSharedMemorySize,
                               SMEM_GEMM_BYTES);
    dim3 grid(NT, MM/128);
    k_gemm<<<grid, 256, SMEM_GEMM_BYTES>>>(x, bias, out);
}

// round 16
// speedup vs baseline: 1.0823x; 1.0150x over previous
#include <cuda_runtime.h>
#include <cuda_fp16.h>
#include <cstdint>
#include <math.h>

// Problem constants
#define BB   8
#define SS   8192
#define HH   768
#define MM   (BB*SS)      // 65536 GEMM rows
#define KK   768          // GEMM K
#define NT   24           // number of 32-wide a/g column tiles (768/32)
#define LAM  0.1f

#define BKT  64           // GEMM k-tile (fp16 elements; 128B per row)
#define KITR (KK/BKT)     // 12
#define BNR  64           // B rows per tile (32 a + 32 g)
#define A_STG_H (128*64)  // 8192 halves
#define B_STG_H (BNR*64)  // 4096 halves
#define STG_H   (A_STG_H + B_STG_H)       // 12288 halves = 24KB
#define SMEM_GEMM_BYTES (3*STG_H*2)       // 73728 -> 72KB (3 CTAs/SM = 216KB)
#define CS_OFF  38912     // Cs at bytes [38912, 73728) — written after all stage reads
// Xs at bytes [0, 16384) — stage-0 region, dead when the prefetch issues (kt = KITR-1)

#define WPREP_N4   (NT*BNR*KK/4)          // 294912 float4 groups
#define WPREP_BLKS ((WPREP_N4 + 255)/256) // 1152

// ---------------- device scratch ----------------
__device__ __half g_v[(size_t)MM*HH];       // silu(x*D + conv) in fp16 (100MB)
__device__ __half g_w[NT*BNR*KK];           // W permuted: [nT][64 rows: 32 a | 32 g][K]
__device__ float  g_tapv[HH*SS];
__device__ int    g_tapi[HH*SS];
__device__ int    g_nnz[HH];

// ---------------- helpers ----------------
__device__ __forceinline__ void cp16(void* s, const void* g) {
    uint32_t sa = (uint32_t)__cvta_generic_to_shared(s);
    asm volatile("cp.async.cg.shared.global [%0], [%1], 16;" :: "r"(sa), "l"(g));
}
__device__ __forceinline__ void cp_commit() { asm volatile("cp.async.commit_group;"); }

__device__ __forceinline__ void ldmx4(uint32_t& r0, uint32_t& r1, uint32_t& r2, uint32_t& r3,
                                      uint32_t addr) {
    asm volatile("ldmatrix.sync.aligned.m8n8.x4.shared.b16 {%0,%1,%2,%3}, [%4];"
                 : "=r"(r0), "=r"(r1), "=r"(r2), "=r"(r3) : "r"(addr));
}

__device__ __forceinline__ void mma_f16(float c[4], const uint32_t a[4], const uint32_t b[2]) {
    asm("mma.sync.aligned.m16n8k16.row.col.f32.f16.f16.f32 "
        "{%0,%1,%2,%3}, {%4,%5,%6,%7}, {%8,%9}, {%0,%1,%2,%3};"
        : "+f"(c[0]), "+f"(c[1]), "+f"(c[2]), "+f"(c[3])
        : "r"(a[0]), "r"(a[1]), "r"(a[2]), "r"(a[3]), "r"(b[0]), "r"(b[1]));
}

// ---------------- kernel 1: fused soft-threshold taps + W permute (float4) ----
// Blocks [0, HH): per-channel tap compaction (vectorized reads).
// Blocks [HH, HH+WPREP_BLKS): W permute/convert, 4 elements per thread.
__global__ void k_prep(const float* __restrict__ ker, const float* __restrict__ W) {
    if (blockIdx.x < HH) {
        __shared__ int cnt;
        const int h = blockIdx.x;
        if (threadIdx.x == 0) cnt = 0;
        __syncthreads();
        const float* kr = ker + (size_t)h*SS;
        for (int t4 = threadIdx.x*4; t4 < SS; t4 += blockDim.x*4) {
            float4 kv = *(const float4*)(kr + t4);
            const float kvv[4] = { kv.x, kv.y, kv.z, kv.w };
            #pragma unroll
            for (int c = 0; c < 4; c++) {
                float av = fabsf(kvv[c]) - LAM;
                if (av > 0.0f) {
                    int p = atomicAdd(&cnt, 1);
                    g_tapv[(size_t)h*SS + p] = copysignf(av, kvv[c]);
                    g_tapi[(size_t)h*SS + p] = t4 + c;
                }
            }
        }
        __syncthreads();
        if (threadIdx.x == 0) g_nnz[h] = cnt;
    } else {
        int i4 = (blockIdx.x - HH) * blockDim.x + threadIdx.x;
        if (i4 >= WPREP_N4) return;
        int k4 = (i4 % (KK/4)) * 4;
        int r  = (i4 / (KK/4)) % BNR;
        int nT = i4 / (BNR*(KK/4));
        int srcRow = (r < 32) ? (nT*32 + r) : (768 + nT*32 + (r - 32));
        float4 w = *(const float4*)(W + (size_t)srcRow*KK + k4);
        __half2 h01 = __floats2half2_rn(w.x, w.y);
        __half2 h23 = __floats2half2_rn(w.z, w.w);
        uint2 o = { *(uint32_t*)&h01, *(uint32_t*)&h23 };
        *(uint2*)(g_w + (size_t)i4*4) = o;
    }
}

// ---------------- kernel 2: v = silu(x*D + sparse_conv) -> fp16, 8 h/thread ---
__global__ void k_v(const float* __restrict__ x, const float* __restrict__ D) {
    int i8 = blockIdx.x * blockDim.x + threadIdx.x;   // index over M*H/8
    int m  = i8 / (HH/8);
    int h0 = (i8 - m*(HH/8)) * 8;
    const float4 xv0 = *(const float4*)(x + (size_t)m*HH + h0);
    const float4 xv1 = *(const float4*)(x + (size_t)m*HH + h0 + 4);
    const float4 dv0 = *(const float4*)(D + h0);
    const float4 dv1 = *(const float4*)(D + h0 + 4);
    float y[8] = { xv0.x*dv0.x, xv0.y*dv0.y, xv0.z*dv0.z, xv0.w*dv0.w,
                   xv1.x*dv1.x, xv1.y*dv1.y, xv1.z*dv1.z, xv1.w*dv1.w };
    const int4 nn0 = *(const int4*)(g_nnz + h0);
    const int4 nn1 = *(const int4*)(g_nnz + h0 + 4);
    if (nn0.x|nn0.y|nn0.z|nn0.w|nn1.x|nn1.y|nn1.z|nn1.w) {  // general conv path
        const int s = m & (SS-1);
        const int nnc[8] = { nn0.x, nn0.y, nn0.z, nn0.w, nn1.x, nn1.y, nn1.z, nn1.w };
        for (int c = 0; c < 8; c++) {
            const int h = h0 + c;
            for (int j = 0; j < nnc[c]; j++) {
                int t = g_tapi[(size_t)h*SS + j];
                if (t <= s) y[c] += g_tapv[(size_t)h*SS + j] * x[(size_t)(m - t)*HH + h];
            }
        }
    }
    __half2 o[4];
    #pragma unroll
    for (int c = 0; c < 4; c++) {
        float a = y[2*c],   sa = a / (1.0f + __expf(-a));
        float b = y[2*c+1], sb = b / (1.0f + __expf(-b));
        o[c] = __floats2half2_rn(sa, sb);
    }
    *(uint4*)(g_v + (size_t)m*HH + h0) = *(uint4*)o;   // single 16B store
}

// ---------------- kernel 3: fp16 GEMM + bias + GLU + residual -----------------
// CTA tile: C[128 x 64]; local cols [0,32)=a, [32,64)=g (same h).
// 8 warps: 4 in M x 2 in N. 3-stage cp.async pipeline (1 barrier/kt), 3 CTAs/SM.
// x-residual prefetch issued INSIDE the last kt iteration (full-MMA-block overlap).
__global__ void __launch_bounds__(256, 3)
k_gemm(const float* __restrict__ x, const float* __restrict__ bias,
       float* __restrict__ out) {
    extern __shared__ __align__(16) char smraw[];
    __half* St = (__half*)smraw;               // 3 stages of [A 128x64 | B 64x64]

    const int tid  = threadIdx.x;
    const int warp = tid >> 5, lane = tid & 31;
    const int g    = lane >> 2, t = lane & 3;
    const int wm   = (warp & 3) * 32;    // warp M offset (4 warps in M)
    const int wn   = (warp >> 2) * 32;   // warp N offset (2 warps in N)
    const int nT   = blockIdx.x;
    const int m0   = blockIdx.y * 128;

    const __half* gA = g_v + (size_t)m0*KK;
    const __half* gB = g_w + (size_t)nT*BNR*KK;

    const int jl = (lane >> 3) & 1;
    const int jh = (lane >> 3) >> 1;
    const int ri = lane & 7;
    const int ar0 = wm + jl*8 + ri;
    int brow[2];
    #pragma unroll
    for (int p = 0; p < 2; p++) brow[p] = wn + (2*p + jh)*8 + ri;

    const uint32_t smS = (uint32_t)__cvta_generic_to_shared(St);
    float* Xs = (float*)smraw;            // [128][32] at bytes [0, 16384)

    float c[2][4][4];
    #pragma unroll
    for (int i = 0; i < 2; i++)
        #pragma unroll
        for (int j = 0; j < 4; j++)
            #pragma unroll
            for (int q = 0; q < 4; q++) c[i][j][q] = 0.0f;

    #define ISSUE_STAGE(stg, kt_)                                              \
    {                                                                          \
        const int k0_ = (kt_) * BKT;                                           \
        _Pragma("unroll")                                                      \
        for (int i_ = 0; i_ < 6; i_++) {                                       \
            int li_ = tid + i_*256;                                            \
            int r_  = li_ >> 3, cc_ = li_ & 7;                                 \
            const __half* src_ = (r_ < 128)                                    \
                ? gA + (size_t)r_*KK + k0_ + cc_*8                             \
                : gB + (size_t)(r_-128)*KK + k0_ + cc_*8;                      \
            cp16(St + (stg)*STG_H + r_*64 + ((cc_ ^ (r_ & 7)) << 3), src_);    \
        }                                                                      \
    }

    ISSUE_STAGE(0, 0); cp_commit();
    ISSUE_STAGE(1, 1); cp_commit();

    for (int kt = 0; kt < KITR; kt++) {
        asm volatile("cp.async.wait_group 1;");
        __syncthreads();
        if (kt + 2 < KITR) {
            ISSUE_STAGE((kt+2)%3, kt+2);
        } else if (kt == KITR - 1) {
            // stage 0 region is dead (last read kt=KITR-3, barriers passed):
            // prefetch x-residual tile (128 x 32 floats = 16KB) into it.
            const float* gx = x + (size_t)m0*HH + nT*32;
            #pragma unroll
            for (int i = 0; i < 4; i++) {
                int li = tid + i*256;
                int r = li >> 3, cc = li & 7;
                cp16(Xs + r*32 + cc*4, gx + (size_t)r*HH + cc*4);
            }
        }
        cp_commit();

        const uint32_t A_ = smS + (uint32_t)((kt%3)*STG_H)*2u;
        const uint32_t B_ = A_ + (uint32_t)A_STG_H*2u;

        #pragma unroll
        for (int ks = 0; ks < 4; ks++) {
            uint32_t af[2][4], bf[4][2];
            const int kcA = 2*ks + jh;
            #pragma unroll
            for (int mt = 0; mt < 2; mt++) {
                int r_ = ar0 + mt*16;
                uint32_t addr = A_ + (uint32_t)(r_*128 + ((kcA ^ (r_ & 7)) << 4));
                ldmx4(af[mt][0], af[mt][1], af[mt][2], af[mt][3], addr);
            }
            const int kcB = 2*ks + jl;
            #pragma unroll
            for (int p = 0; p < 2; p++) {
                int r_ = brow[p];
                uint32_t addr = B_ + (uint32_t)(r_*128 + ((kcB ^ (r_ & 7)) << 4));
                ldmx4(bf[2*p][0], bf[2*p][1], bf[2*p+1][0], bf[2*p+1][1], addr);
            }
            #pragma unroll
            for (int mt = 0; mt < 2; mt++)
                #pragma unroll
                for (int nt = 0; nt < 4; nt++)
                    mma_f16(c[mt][nt], af[mt], bf[nt]);
        }
    }
    __syncthreads();                      // all stage reads done

    // ---- stage C through smem (region disjoint from pending Xs prefetch) ----
    float* Cs = (float*)(smraw + CS_OFF); // [128][68] = 34.8KB at [38912, 73728)
    #pragma unroll
    for (int mt = 0; mt < 2; mt++)
        #pragma unroll
        for (int nt = 0; nt < 4; nt++) {
            int r = wm + mt*16 + g, cc = wn + nt*8 + 2*t;
            Cs[ r   *68 + cc    ] = c[mt][nt][0];
            Cs[ r   *68 + cc + 1] = c[mt][nt][1];
            Cs[(r+8)*68 + cc    ] = c[mt][nt][2];
            Cs[(r+8)*68 + cc + 1] = c[mt][nt][3];
        }
    asm volatile("cp.async.wait_group 0;");   // Xs landed
    __syncthreads();

    // ---- bias + GLU + residual, write final output ----
    #pragma unroll
    for (int i = 0; i < 16; i++) {
        int idx = i*256 + tid;            // 128*32 outputs
        int r = idx >> 5, j = idx & 31;
        int h = nT*32 + j;
        float a  = Cs[r*68 + j     ] + bias[h];
        float gg = Cs[r*68 + j + 32] + bias[h + 768];
        float sg = 1.0f / (1.0f + __expf(-gg));
        out[(size_t)(m0 + r)*HH + h] = a * sg + Xs[r*32 + j];
    }
    #undef ISSUE_STAGE
}

// ---------------- launch ----------------
extern "C" void kernel_launch(void* const* d_in, const int* in_sizes, int n_in,
                              void* d_out, int out_size) {
    const float* x    = (const float*)d_in[0];   // (8, 8192, 768)
    const float* ker  = (const float*)d_in[1];   // (1, 768, 8192)
    const float* D    = (const float*)d_in[2];   // (1, 768)
    const float* W    = (const float*)d_in[3];   // (1536, 768)
    const float* bias = (const float*)d_in[4];   // (1536,)
    float* out = (float*)d_out;                  // (8, 8192, 768)

    k_prep<<<HH + WPREP_BLKS, 256>>>(ker, W);
    k_v<<<(MM*(HH/8))/256, 256>>>(x, D);

    (void)cudaFuncSetAttribute(k_gemm, cudaFuncAttributeMaxDynamicSharedMemorySize,
                               SMEM_GEMM_BYTES);
    dim3 grid(NT, MM/128);
    k_gemm<<<grid, 256, SMEM_GEMM_BYTES>>>(x, bias, out);
}